// round 5
// baseline (speedup 1.0000x reference)
#include <cuda_runtime.h>
#include <cstdint>

// LRAP loss, B x C = 16384 x 2048.
// Atomic-free bucket ranking: quantile-balanced 64 buckets, warp-match
// histograms, plain-STS scatter, per-bucket all-pairs refine via shuffles.

#define NCLS    2048
#define THREADS 512
#define NWARP   16
#define NBIN    64

__device__ double g_rowscore[16384];
__device__ double g_partial[64];

// Normal quantiles Phi^-1((i+1)/64), i = 0..62. Only monotonicity matters
// for correctness; accuracy only affects bucket load balance.
__constant__ float QTAB[63] = {
    -2.1539f, -1.8627f, -1.6759f, -1.5341f, -1.4178f, -1.3180f, -1.2299f,
    -1.1503f, -1.0775f, -1.0100f, -0.9468f, -0.8871f, -0.8305f, -0.7764f,
    -0.7245f, -0.6745f, -0.6261f, -0.5791f, -0.5334f, -0.4888f, -0.4451f,
    -0.4023f, -0.3601f, -0.3186f, -0.2776f, -0.2372f, -0.1971f, -0.1573f,
    -0.1178f, -0.0784f, -0.0392f,  0.0000f,  0.0392f,  0.0784f,  0.1178f,
     0.1573f,  0.1971f,  0.2372f,  0.2776f,  0.3186f,  0.3601f,  0.4023f,
     0.4451f,  0.4888f,  0.5334f,  0.5791f,  0.6261f,  0.6745f,  0.7245f,
     0.7764f,  0.8305f,  0.8871f,  0.9468f,  1.0100f,  1.0775f,  1.1503f,
     1.2299f,  1.3180f,  1.4178f,  1.5341f,  1.6759f,  1.8627f,  2.1539f
};

__device__ __forceinline__ uint32_t orderFloat(float f) {
    uint32_t u = __float_as_uint(f);
    return (u & 0x80000000u) ? ~u : (u | 0x80000000u);  // monotone increasing
}

__global__ __launch_bounds__(THREADS, 3)
void lrap_row_kernel(const float* __restrict__ preds,
                     const float* __restrict__ labels) {
    const int row  = blockIdx.x;
    const int t    = threadIdx.x;
    const int lane = t & 31;
    const int w    = t >> 5;
    const uint32_t lmask_lt = (1u << lane) - 1u;

    __shared__ float    qsh[63];
    __shared__ uint32_t wcnt[NBIN * 17];      // [bin][warp] packed pos<<16|cnt
    __shared__ uint32_t binTot[NBIN];
    __shared__ uint32_t binBase[NBIN + 1];    // packed exclusive prefix
    __shared__ uint32_t scat[NCLS];           // bucket-grouped keys
    __shared__ double   redS[NWARP];
    __shared__ int      redN[NWARP];

    // ---- init smem ----
    if (t < 63) qsh[t] = QTAB[t];
    wcnt[t] = 0u; wcnt[t + 512] = 0u;
    if (t < NBIN * 17 - 1024) wcnt[t + 1024] = 0u;
    __syncthreads();

    // ---- load + bucket (quantile binary search) ----
    const float4 pv = ((const float4*)(preds  + (size_t)row * NCLS))[t];
    const float4 lv = ((const float4*)(labels + (size_t)row * NCLS))[t];
    const float px[4] = {pv.x, pv.y, pv.z, pv.w};
    const float lx[4] = {lv.x, lv.y, lv.z, lv.w};

    uint32_t key[4];
    int      bkt[4];
    uint32_t woff[4];

    #pragma unroll
    for (int c = 0; c < 4; c++) {
        uint32_t lab = (lx[c] > 0.5f) ? 1u : 0u;
        key[c] = (orderFloat(px[c]) & 0xFFFFFFFEu) | lab;
        int bin = 0;
        #pragma unroll
        for (int s = 32; s; s >>= 1) {
            int nb = bin + s;
            if (nb <= 63 && px[c] >= qsh[nb - 1]) bin = nb;
        }
        bkt[c] = 63 - bin;   // bucket 0 = largest preds = best ranks
    }

    // ---- atomic-free warp histograms: match_any + leader RMW ----
    #pragma unroll
    for (int c = 0; c < 4; c++) {
        int b = bkt[c];
        uint32_t mlab = __ballot_sync(0xffffffffu, key[c] & 1u);
        uint32_t mask = __match_any_sync(0xffffffffu, b);
        uint32_t lr   = __popc(mask & lmask_lt);
        uint32_t cur  = wcnt[b * 17 + w];
        __syncwarp();
        if (lr == 0) {
            uint32_t cnt = __popc(mask);
            uint32_t pos = __popc(mask & mlab);
            wcnt[b * 17 + w] = cur + cnt + (pos << 16);
        }
        __syncwarp();
        woff[c] = (cur & 0xFFFFu) + lr;
    }
    __syncthreads();

    // ---- scan 1: per-bin exclusive over warps (in place), bin totals ----
    if (t < NBIN) {
        uint32_t run = 0;
        #pragma unroll
        for (int w2 = 0; w2 < NWARP; w2++) {
            uint32_t v = wcnt[t * 17 + w2];
            wcnt[t * 17 + w2] = run;
            run += v;
        }
        binTot[t] = run;
    }
    __syncthreads();

    // ---- scan 2: exclusive over 64 bins (warp 0, 2 bins/lane) ----
    if (t < 32) {
        uint32_t a  = binTot[2 * t];
        uint32_t b2 = binTot[2 * t + 1];
        uint32_t x  = a + b2;
        uint32_t inc = x;
        #pragma unroll
        for (int off = 1; off < 32; off <<= 1) {
            uint32_t n = __shfl_up_sync(0xffffffffu, inc, off);
            if (t >= off) inc += n;
        }
        uint32_t excl = inc - x;
        binBase[2 * t]     = excl;
        binBase[2 * t + 1] = excl + a;
        if (t == 31) binBase[NBIN] = inc;
    }
    __syncthreads();

    // ---- scatter keys into bucket order (plain STS, unique slots) ----
    #pragma unroll
    for (int c = 0; c < 4; c++) {
        int b = bkt[c];
        uint32_t addr = (binBase[b] & 0xFFFFu)
                      + (wcnt[b * 17 + w] & 0xFFFFu)
                      + woff[c];
        scat[addr] = key[c];
    }
    __syncthreads();

    // ---- refine: warp w owns bins 4w..4w+3; all-pairs via shuffles ----
    float sc = 0.0f;
    int npos = 0;
    #pragma unroll
    for (int bi = 0; bi < 4; bi++) {
        int b = (w << 2) + bi;
        uint32_t pb = binBase[b], pe = binBase[b + 1];
        int st = (int)(pb & 0xFFFFu), en = (int)(pe & 0xFFFFu);
        int cnt = en - st;
        uint32_t pB = pb >> 16;
        int nch = (cnt + 31) >> 5;
        for (int ci = 0; ci < nch; ci++) {
            int myidx = st + (ci << 5) + lane;
            bool valid = myidx < en;
            uint32_t kme = valid ? scat[myidx] : 0u;
            uint32_t gt = 0, pg = 0;
            for (int cj = 0; cj < nch; cj++) {
                int oidx = st + (cj << 5) + lane;
                uint32_t ko = (oidx < en) ? scat[oidx] : 0u;
                int ccnt = min(32, en - st - (cj << 5));
                for (int s2 = 0; s2 < ccnt; s2++) {
                    uint32_t v = __shfl_sync(0xffffffffu, ko, s2);
                    if (v > kme) { gt++; pg += (v & 1u); }
                }
            }
            if (valid && (kme & 1u)) {
                sc += __fdividef((float)(pB + pg + 1u),
                                 (float)((uint32_t)st + gt + 1u));
                npos++;
            }
        }
    }

    // ---- block reduce, per-row score ----
    double d = (double)sc;
    #pragma unroll
    for (int off = 16; off; off >>= 1) {
        d    += __shfl_down_sync(0xffffffffu, d, off);
        npos += __shfl_down_sync(0xffffffffu, npos, off);
    }
    if (lane == 0) { redS[w] = d; redN[w] = npos; }
    __syncthreads();
    if (t == 0) {
        double tot = 0.0; int np = 0;
        #pragma unroll
        for (int w2 = 0; w2 < NWARP; w2++) { tot += redS[w2]; np += redN[w2]; }
        g_rowscore[row] = tot / (double)np;
    }
}

__global__ __launch_bounds__(256)
void lrap_reduce1_kernel(int B) {
    __shared__ double red[8];
    const int t = threadIdx.x;
    const int per = (B + 63) / 64;
    const int base = blockIdx.x * per;
    double s = 0.0;
    for (int i = t; i < per; i += 256) {
        int idx = base + i;
        if (idx < B) s += g_rowscore[idx];
    }
    const int lane = t & 31, wd = t >> 5;
    #pragma unroll
    for (int off = 16; off; off >>= 1) s += __shfl_down_sync(0xffffffffu, s, off);
    if (lane == 0) red[wd] = s;
    __syncthreads();
    if (t == 0) {
        double tot = 0.0;
        #pragma unroll
        for (int w2 = 0; w2 < 8; w2++) tot += red[w2];
        g_partial[blockIdx.x] = tot;
    }
}

__global__ void lrap_reduce2_kernel(float* __restrict__ out, int B) {
    const int lane = threadIdx.x;
    double s = g_partial[lane] + g_partial[lane + 32];
    #pragma unroll
    for (int off = 16; off; off >>= 1) s += __shfl_down_sync(0xffffffffu, s, off);
    if (lane == 0) out[0] = (float)(s / (double)B);
}

extern "C" void kernel_launch(void* const* d_in, const int* in_sizes, int n_in,
                              void* d_out, int out_size) {
    const float* preds  = (const float*)d_in[0];
    const float* labels = (const float*)d_in[1];
    float* out = (float*)d_out;

    int B = in_sizes[0] / NCLS;
    if (B > 16384) B = 16384;   // scratch capacity

    lrap_row_kernel<<<B, THREADS>>>(preds, labels);
    lrap_reduce1_kernel<<<64, 256>>>(B);
    lrap_reduce2_kernel<<<1, 32>>>(out, B);
}

// round 6
// speedup vs baseline: 3.0208x; 3.0208x over previous
#include <cuda_runtime.h>
#include <cstdint>

// LRAP loss, B x C = 16384 x 2048.
// 2048 fine bins; ONE shared atomic per element (packed count|pos, return
// value = scatter slot); in-place packed exclusive scan; plain-STS scatter;
// per-positive tiny-bucket refine (avg bucket size ~1-3).

#define NCLS    2048
#define THREADS 256
#define EPT     8

__device__ double g_rowscore[16384];
__device__ double g_partial[64];

__device__ __forceinline__ uint32_t orderFloat(float f) {
    uint32_t u = __float_as_uint(f);
    return (u & 0x80000000u) ? ~u : (u | 0x80000000u);  // monotone increasing
}

__global__ __launch_bounds__(THREADS, 5)
void lrap_row_kernel(const float* __restrict__ preds,
                     const float* __restrict__ labels) {
    const int row  = blockIdx.x;
    const int t    = threadIdx.x;
    const int lane = t & 31;
    const int w    = t >> 5;

    __shared__ uint32_t bins[NCLS + 1];  // hist (lo16 cnt, hi16 pos) -> excl base
    __shared__ uint32_t scat[NCLS];      // bucket-grouped 32-bit keys
    __shared__ uint32_t warpSums[8];
    __shared__ double   redS[8];
    __shared__ int      redN[8];

    // ---- zero histogram ----
    *(uint4*)&bins[t * 8]     = make_uint4(0u, 0u, 0u, 0u);
    *(uint4*)&bins[t * 8 + 4] = make_uint4(0u, 0u, 0u, 0u);
    __syncthreads();

    // ---- phase A: load 8 elements, bin, ONE atomic per element ----
    const float4* p4 = (const float4*)(preds  + (size_t)row * NCLS);
    const float4* l4 = (const float4*)(labels + (size_t)row * NCLS);

    uint32_t key[EPT];
    uint32_t combo[EPT];   // (bin << 16) | within-bin slot
    uint32_t labm = 0;

    #pragma unroll
    for (int i = 0; i < 2; i++) {
        const int q = t + i * THREADS;
        const float4 pv = p4[q];
        const float4 lv = l4[q];
        const float px[4] = {pv.x, pv.y, pv.z, pv.w};
        const float lx[4] = {lv.x, lv.y, lv.z, lv.w};
        #pragma unroll
        for (int c = 0; c < 4; c++) {
            const int e = i * 4 + c;
            uint32_t lab = (lx[c] > 0.5f) ? 1u : 0u;
            labm |= lab << e;
            key[e] = (orderFloat(px[c]) & 0xFFFFFFFEu) | lab;
            int bin = __float2int_rd(fmaf(px[c], 256.0f, 1024.0f));
            bin = max(0, min(2047, bin));
            int b = 2047 - bin;              // bin 0 = largest preds = best rank
            uint32_t old = atomicAdd(&bins[b], 1u + (lab << 16));
            combo[e] = ((uint32_t)b << 16) | (old & 0xFFFFu);
        }
    }
    __syncthreads();

    // ---- phase B: in-place packed exclusive prefix over 2048 counters ----
    uint32_t loc[EPT];
    uint32_t s = 0;
    {
        const uint4 h0 = *(const uint4*)&bins[t * 8];
        const uint4 h1 = *(const uint4*)&bins[t * 8 + 4];
        const uint32_t h[EPT] = {h0.x, h0.y, h0.z, h0.w, h1.x, h1.y, h1.z, h1.w};
        #pragma unroll
        for (int i = 0; i < EPT; i++) { loc[i] = s; s += h[i]; }
    }
    uint32_t inc = s;
    #pragma unroll
    for (int off = 1; off < 32; off <<= 1) {
        uint32_t n = __shfl_up_sync(0xffffffffu, inc, off);
        if (lane >= off) inc += n;
    }
    if (lane == 31) warpSums[w] = inc;
    __syncthreads();
    if (t == 0) {
        uint32_t acc = 0;
        #pragma unroll
        for (int w2 = 0; w2 < 8; w2++) { uint32_t v = warpSums[w2]; warpSums[w2] = acc; acc += v; }
    }
    __syncthreads();
    const uint32_t exclT = warpSums[w] + (inc - s);
    {
        uint4 b0 = make_uint4(exclT + loc[0], exclT + loc[1], exclT + loc[2], exclT + loc[3]);
        uint4 b1 = make_uint4(exclT + loc[4], exclT + loc[5], exclT + loc[6], exclT + loc[7]);
        *(uint4*)&bins[t * 8]     = b0;
        *(uint4*)&bins[t * 8 + 4] = b1;
    }
    if (t == THREADS - 1) bins[NCLS] = exclT + s;   // total (2048 | npos<<16)
    __syncthreads();

    // ---- phase C: scatter keys (plain STS; slot came from the atomic) ----
    #pragma unroll
    for (int e = 0; e < EPT; e++) {
        uint32_t b   = combo[e] >> 16;
        uint32_t off = combo[e] & 0xFFFFu;
        scat[(bins[b] & 0xFFFFu) + off] = key[e];
    }
    __syncthreads();

    // ---- phase D: per-positive exact rank via tiny in-bucket scan ----
    float sc = 0.0f;
    int npos = __popc(labm & 0xFFu);
    #pragma unroll
    for (int e = 0; e < EPT; e++) {
        if ((labm >> e) & 1u) {
            uint32_t b  = combo[e] >> 16;
            uint32_t pb = bins[b];
            uint32_t pe = bins[b + 1];
            uint32_t st  = pb & 0xFFFFu;
            uint32_t en  = pe & 0xFFFFu;
            uint32_t pB  = pb >> 16;          // positives in strictly-better bins
            uint32_t k   = key[e];
            uint32_t gt = 0, pg = 0;
            for (uint32_t m = st; m < en; m++) {
                uint32_t k2 = scat[m];
                if (k2 > k) { gt++; pg += (k2 & 1u); }
            }
            sc += __fdividef((float)(pB + pg + 1u), (float)(st + gt + 1u));
        }
    }

    // ---- phase E: block reduce, per-row score ----
    double d = (double)sc;
    #pragma unroll
    for (int off = 16; off; off >>= 1) {
        d    += __shfl_down_sync(0xffffffffu, d, off);
        npos += __shfl_down_sync(0xffffffffu, npos, off);
    }
    if (lane == 0) { redS[w] = d; redN[w] = npos; }
    __syncthreads();
    if (t == 0) {
        double tot = 0.0; int np = 0;
        #pragma unroll
        for (int w2 = 0; w2 < 8; w2++) { tot += redS[w2]; np += redN[w2]; }
        g_rowscore[row] = tot / (double)np;
    }
}

__global__ __launch_bounds__(256)
void lrap_reduce1_kernel(int B) {
    __shared__ double red[8];
    const int t = threadIdx.x;
    const int per = (B + 63) / 64;
    const int base = blockIdx.x * per;
    double s = 0.0;
    for (int i = t; i < per; i += 256) {
        int idx = base + i;
        if (idx < B) s += g_rowscore[idx];
    }
    const int lane = t & 31, wd = t >> 5;
    #pragma unroll
    for (int off = 16; off; off >>= 1) s += __shfl_down_sync(0xffffffffu, s, off);
    if (lane == 0) red[wd] = s;
    __syncthreads();
    if (t == 0) {
        double tot = 0.0;
        #pragma unroll
        for (int w2 = 0; w2 < 8; w2++) tot += red[w2];
        g_partial[blockIdx.x] = tot;
    }
}

__global__ void lrap_reduce2_kernel(float* __restrict__ out, int B) {
    const int lane = threadIdx.x;
    double s = g_partial[lane] + g_partial[lane + 32];
    #pragma unroll
    for (int off = 16; off; off >>= 1) s += __shfl_down_sync(0xffffffffu, s, off);
    if (lane == 0) out[0] = (float)(s / (double)B);
}

extern "C" void kernel_launch(void* const* d_in, const int* in_sizes, int n_in,
                              void* d_out, int out_size) {
    const float* preds  = (const float*)d_in[0];
    const float* labels = (const float*)d_in[1];
    float* out = (float*)d_out;

    int B = in_sizes[0] / NCLS;
    if (B > 16384) B = 16384;   // scratch capacity

    lrap_row_kernel<<<B, THREADS>>>(preds, labels);
    lrap_reduce1_kernel<<<64, 256>>>(B);
    lrap_reduce2_kernel<<<1, 32>>>(out, B);
}

// round 8
// speedup vs baseline: 3.2747x; 1.0841x over previous
#include <cuda_runtime.h>
#include <cstdint>

// LRAP loss, B x C = 16384 x 2048.
// 2048 fine bins; ONE shared atomic per element (packed count|pos, return
// value = scatter slot); in-place packed exclusive scan; slot-major
// CONVERGENT refine (adjacent lanes -> adjacent slots -> same bins).

#define NCLS    2048
#define THREADS 256
#define EPT     8

__device__ double g_rowscore[16384];
__device__ double g_partial[64];

__device__ __forceinline__ uint32_t orderFloat(float f) {
    uint32_t u = __float_as_uint(f);
    return (u & 0x80000000u) ? ~u : (u | 0x80000000u);  // monotone increasing
}

__global__ __launch_bounds__(THREADS, 5)
void lrap_row_kernel(const float* __restrict__ preds,
                     const float* __restrict__ labels) {
    const int row  = blockIdx.x;
    const int t    = threadIdx.x;
    const int lane = t & 31;
    const int w    = t >> 5;

    __shared__ uint32_t bins[NCLS + 1];  // hist (lo16 cnt, hi16 pos) -> excl base
    __shared__ uint32_t scat[NCLS];      // bucket-grouped 32-bit keys
    __shared__ uint16_t binof[NCLS];     // slot -> bin id
    __shared__ uint32_t warpSums[8];
    __shared__ double   redS[8];
    __shared__ int      redN[8];

    // ---- zero histogram ----
    *(uint4*)&bins[t * 8]     = make_uint4(0u, 0u, 0u, 0u);
    *(uint4*)&bins[t * 8 + 4] = make_uint4(0u, 0u, 0u, 0u);
    __syncthreads();

    // ---- phase A: load 8 elements, bin, ONE atomic per element ----
    const float4* p4 = (const float4*)(preds  + (size_t)row * NCLS);
    const float4* l4 = (const float4*)(labels + (size_t)row * NCLS);

    uint32_t key[EPT];
    uint32_t combo[EPT];   // (bin << 16) | within-bin arrival slot

    #pragma unroll
    for (int i = 0; i < 2; i++) {
        const int q = t + i * THREADS;
        const float4 pv = p4[q];
        const float4 lv = l4[q];
        const float px[4] = {pv.x, pv.y, pv.z, pv.w};
        const float lx[4] = {lv.x, lv.y, lv.z, lv.w};
        #pragma unroll
        for (int c = 0; c < 4; c++) {
            const int e = i * 4 + c;
            uint32_t lab = (lx[c] > 0.5f) ? 1u : 0u;
            key[e] = (orderFloat(px[c]) & 0xFFFFFFFEu) | lab;
            int bin = __float2int_rd(fmaf(px[c], 256.0f, 1024.0f));
            bin = max(0, min(2047, bin));
            int b = 2047 - bin;              // bin 0 = largest preds = best rank
            uint32_t old = atomicAdd(&bins[b], 1u + (lab << 16));
            combo[e] = ((uint32_t)b << 16) | (old & 0xFFFFu);
        }
    }
    __syncthreads();

    // ---- phase B: in-place packed exclusive prefix over 2048 counters ----
    uint32_t loc[EPT];
    uint32_t s = 0;
    {
        const uint4 h0 = *(const uint4*)&bins[t * 8];
        const uint4 h1 = *(const uint4*)&bins[t * 8 + 4];
        const uint32_t h[EPT] = {h0.x, h0.y, h0.z, h0.w, h1.x, h1.y, h1.z, h1.w};
        #pragma unroll
        for (int i = 0; i < EPT; i++) { loc[i] = s; s += h[i]; }
    }
    uint32_t inc = s;
    #pragma unroll
    for (int off = 1; off < 32; off <<= 1) {
        uint32_t n = __shfl_up_sync(0xffffffffu, inc, off);
        if (lane >= off) inc += n;
    }
    if (lane == 31) warpSums[w] = inc;
    __syncthreads();
    if (t == 0) {
        uint32_t acc = 0;
        #pragma unroll
        for (int w2 = 0; w2 < 8; w2++) { uint32_t v = warpSums[w2]; warpSums[w2] = acc; acc += v; }
    }
    __syncthreads();
    const uint32_t exclT = warpSums[w] + (inc - s);
    {
        uint4 b0 = make_uint4(exclT + loc[0], exclT + loc[1], exclT + loc[2], exclT + loc[3]);
        uint4 b1 = make_uint4(exclT + loc[4], exclT + loc[5], exclT + loc[6], exclT + loc[7]);
        *(uint4*)&bins[t * 8]     = b0;
        *(uint4*)&bins[t * 8 + 4] = b1;
    }
    if (t == THREADS - 1) bins[NCLS] = exclT + s;   // total (2048 | npos<<16)
    __syncthreads();

    // ---- phase C: scatter keys + bin ids (plain STS; slot from atomic) ----
    #pragma unroll
    for (int e = 0; e < EPT; e++) {
        uint32_t b    = combo[e] >> 16;
        uint32_t off  = combo[e] & 0xFFFFu;
        uint32_t slot = (bins[b] & 0xFFFFu) + off;
        scat[slot]  = key[e];
        binof[slot] = (uint16_t)b;
    }
    __syncthreads();

    // ---- phase D: slot-major convergent refine ----
    // Adjacent lanes read adjacent slots: same bins, identical loop bounds,
    // broadcast LDS -> minimal divergence.
    float sc = 0.0f;
    int npos = 0;
    #pragma unroll
    for (int i = 0; i < EPT; i++) {
        const int m = t + i * THREADS;
        const uint32_t k = scat[m];
        if (k & 1u) {
            const int b = (int)binof[m];
            const uint32_t pb = bins[b];
            const uint32_t st = pb & 0xFFFFu;
            const uint32_t pB = pb >> 16;     // positives in strictly-better bins
            const uint32_t en = bins[b + 1] & 0xFFFFu;
            uint32_t gt = 0, pg = 0;
            for (uint32_t mm = st; mm < en; mm++) {
                const uint32_t k2 = scat[mm];
                if (k2 > k) { gt++; pg += (k2 & 1u); }
            }
            sc += __fdividef((float)(pB + pg + 1u), (float)(st + gt + 1u));
            npos++;
        }
    }

    // ---- phase E: block reduce, per-row score ----
    double d = (double)sc;
    #pragma unroll
    for (int off = 16; off; off >>= 1) {
        d    += __shfl_down_sync(0xffffffffu, d, off);
        npos += __shfl_down_sync(0xffffffffu, npos, off);
    }
    if (lane == 0) { redS[w] = d; redN[w] = npos; }
    __syncthreads();
    if (t == 0) {
        double tot = 0.0; int np = 0;
        #pragma unroll
        for (int w2 = 0; w2 < 8; w2++) { tot += redS[w2]; np += redN[w2]; }
        g_rowscore[row] = tot / (double)np;
    }
}

__global__ __launch_bounds__(256)
void lrap_reduce1_kernel(int B) {
    __shared__ double red[8];
    const int t = threadIdx.x;
    const int per = (B + 63) / 64;
    const int base = blockIdx.x * per;
    double s = 0.0;
    for (int i = t; i < per; i += 256) {
        int idx = base + i;
        if (idx < B) s += g_rowscore[idx];
    }
    const int lane = t & 31, wd = t >> 5;
    #pragma unroll
    for (int off = 16; off; off >>= 1) s += __shfl_down_sync(0xffffffffu, s, off);
    if (lane == 0) red[wd] = s;
    __syncthreads();
    if (t == 0) {
        double tot = 0.0;
        #pragma unroll
        for (int w2 = 0; w2 < 8; w2++) tot += red[w2];
        g_partial[blockIdx.x] = tot;
    }
}

__global__ void lrap_reduce2_kernel(float* __restrict__ out, int B) {
    const int lane = threadIdx.x;
    double s = g_partial[lane] + g_partial[lane + 32];
    #pragma unroll
    for (int off = 16; off; off >>= 1) s += __shfl_down_sync(0xffffffffu, s, off);
    if (lane == 0) out[0] = (float)(s / (double)B);
}

extern "C" void kernel_launch(void* const* d_in, const int* in_sizes, int n_in,
                              void* d_out, int out_size) {
    const float* preds  = (const float*)d_in[0];
    const float* labels = (const float*)d_in[1];
    float* out = (float*)d_out;

    int B = in_sizes[0] / NCLS;
    if (B > 16384) B = 16384;   // scratch capacity

    lrap_row_kernel<<<B, THREADS>>>(preds, labels);
    lrap_reduce1_kernel<<<64, 256>>>(B);
    lrap_reduce2_kernel<<<1, 32>>>(out, B);
}